// round 15
// baseline (speedup 1.0000x reference)
#include <cuda_runtime.h>
#include <mma.h>
#include <cstdint>

using namespace nvcuda;

// Problem shape (fixed)
constexpr int Bc = 64, Lc = 512, Dc = 256, Fc = 256;
constexpr int MT = 64;            // output rows per CTA
constexpr int KS = 32;            // K slab
constexpr int NSLAB = 768 / KS;   // 24
constexpr int LDA = 40;           // A slab stride (floats)
constexpr int LDB = 264;          // B slab stride
constexpr int LDC = 264;          // epilogue bounce stride

constexpr int ABUF = MT * LDA;            // 2560 floats per A buffer
constexpr int BBUF = KS * LDB;            // 8448 floats per B buffer
constexpr int OFF_B = 2 * ABUF;           // 5120
constexpr int OFF_P = OFF_B + 2 * BBUF;   // 22016
constexpr int SMEMF = OFF_P + 1152;       // 23168 floats = 92672 B (2 CTAs/SM)

// Device scratch (no allocations allowed)
__device__ float g_h1[(size_t)Bc * Lc * Fc];   // conv1 out, tf32-rounded
__device__ float g_xr[(size_t)Bc * Lc * Dc];   // x pre-rounded to tf32
__device__ float g_w[2][768 * Fc];             // weights pre-rounded to tf32
__device__ int   g_ends[Bc * Lc];
__device__ __align__(16) float g_zero[8];      // zero-initialized

// ---------------------------------------------------------------- helpers
__device__ __forceinline__ uint32_t smem_u32(const void* p) {
    uint32_t a;
    asm("{ .reg .u64 t; cvta.to.shared.u64 t, %1; cvt.u32.u64 %0, t; }" : "=r"(a) : "l"(p));
    return a;
}
__device__ __forceinline__ float to_tf32(float x) {
    float r; asm("cvt.rna.tf32.f32 %0, %1;" : "=f"(r) : "f"(x)); return r;
}
__device__ __forceinline__ void cpa16(uint32_t dst, const void* src) {
    asm volatile("cp.async.ca.shared.global [%0], [%1], 16;" :: "r"(dst), "l"(src));
}
#define CPA_COMMIT() asm volatile("cp.async.commit_group;" ::: "memory")
#define CPA_WAIT(n)  asm volatile("cp.async.wait_group %0;" :: "n"(n) : "memory")

// ---------------------------------------------------------------------------
// Prep: round weights / x to tf32 once (keeps GEMM staging cvt-free)
// ---------------------------------------------------------------------------
__global__ void cvt_w(const float* __restrict__ w1, const float* __restrict__ w2)
{
    int i = blockIdx.x * 256 + threadIdx.x;            // float4 idx, 49152 per w
    const float4* s = (const float4*)(blockIdx.y ? w2 : w1);
    float4 v = s[i];
    v.x = to_tf32(v.x); v.y = to_tf32(v.y); v.z = to_tf32(v.z); v.w = to_tf32(v.w);
    ((float4*)g_w[blockIdx.y])[i] = v;
}
__global__ void cvt_x(const float* __restrict__ x)
{
    size_t i = (size_t)blockIdx.x * 256 + threadIdx.x; // float4 idx, 2097152
    float4 v = ((const float4*)x)[i];
    v.x = to_tf32(v.x); v.y = to_tf32(v.y); v.z = to_tf32(v.z); v.w = to_tf32(v.w);
    ((float4*)g_xr)[i] = v;
}

// ---------------------------------------------------------------------------
// Fused conv1d(k=3,same) -> bias -> LN -> ReLU (PASS1 -> g_h1, tf32-rounded)
// PASS2 fuses the 256->1 linear + ReLU into dp.
// tf32 wmma, cp.async double-buffered slabs, 2 CTAs/SM.
// ---------------------------------------------------------------------------
template <int PASS>
__global__ __launch_bounds__(256, 2) void conv_wmma(
    const float* __restrict__ in,   // (B,L,256) already tf32-rounded
    const float* __restrict__ w,    // (768,256) already tf32-rounded
    const float* __restrict__ cb,
    const float* __restrict__ gam,
    const float* __restrict__ bet,
    const float* __restrict__ linw,
    const float* __restrict__ linb,
    float* __restrict__ dp)
{
    extern __shared__ __align__(16) float smf[];
    float* p_cb = smf + OFF_P;
    float* p_g  = p_cb + 256;
    float* p_b  = p_g + 256;
    float* p_lw = p_b + 256;
    float* p_mu = p_lw + 256;   // 64
    float* p_rs = p_mu + 64;    // 64

    const uint32_t smA = smem_u32(smf);
    const uint32_t smB = smA + OFF_B * 4;

    const int tid = threadIdx.x;
    const int b   = blockIdx.y;
    const int l0  = blockIdx.x * MT;
    const float* inb = in + (size_t)b * Lc * Dc;

    // ---- slab staging via cp.async (A: 64x32 with tap baked in; B: 32x256)
    auto stage = [&](int slab, int bufi) {
        const int tap = slab >> 3;            // KS=32 -> 8 slabs per tap
        const int kc0 = (slab & 7) * KS;
        const uint32_t ab = smA + (uint32_t)bufi * (ABUF * 4);
#pragma unroll
        for (int t = 0; t < 2; t++) {         // 512 chunks of 16B
            int i = tid + t * 256;
            int r = i >> 3, c = i & 7;
            int l = l0 + r - 1 + tap;
            const void* src = (l >= 0 && l < Lc)
                ? (const void*)(inb + (size_t)l * Dc + kc0 + c * 4)
                : (const void*)g_zero;
            cpa16(ab + (uint32_t)(r * LDA + c * 4) * 4, src);
        }
        const uint32_t bb = smB + (uint32_t)bufi * (BBUF * 4);
        const float* wsrc = w + (size_t)slab * KS * Fc;
#pragma unroll
        for (int t = 0; t < 8; t++) {         // 2048 chunks of 16B
            int i = tid + t * 256;
            int r = i >> 6, c = i & 63;
            cpa16(bb + (uint32_t)(r * LDB + c * 4) * 4, wsrc + (size_t)r * Fc + c * 4);
        }
    };

    // params (plain loads)
    for (int i = tid; i < Fc; i += 256) {
        p_cb[i] = cb[i]; p_g[i] = gam[i]; p_b[i] = bet[i];
        if (PASS == 2) p_lw[i] = linw[i];
    }

    const int wid = tid >> 5;
    const int wm = wid >> 2;          // 0..1 : 32 rows
    const int wn = wid & 3;           // 0..3 : 64 cols

    wmma::fragment<wmma::accumulator, 16, 16, 8, float> acc[2][4];
#pragma unroll
    for (int mi = 0; mi < 2; mi++)
#pragma unroll
        for (int ni = 0; ni < 4; ni++)
            wmma::fill_fragment(acc[mi][ni], 0.0f);

    stage(0, 0);
    CPA_COMMIT();

    for (int it = 0; it < NSLAB; ++it) {
        if (it + 1 < NSLAB) {
            stage(it + 1, (it + 1) & 1);
            CPA_COMMIT();
            CPA_WAIT(1);               // slab `it` landed; `it+1` in flight
        } else {
            CPA_WAIT(0);
        }
        __syncthreads();

        const float* As = smf + (it & 1) * ABUF;
        const float* Bs = smf + OFF_B + (it & 1) * BBUF;
#pragma unroll
        for (int k8 = 0; k8 < KS; k8 += 8) {
            wmma::fragment<wmma::matrix_a, 16, 16, 8, wmma::precision::tf32, wmma::row_major> af[2];
            wmma::fragment<wmma::matrix_b, 16, 16, 8, wmma::precision::tf32, wmma::row_major> bf[4];
#pragma unroll
            for (int mi = 0; mi < 2; mi++)
                wmma::load_matrix_sync(af[mi], As + (wm * 32 + mi * 16) * LDA + k8, LDA);
#pragma unroll
            for (int ni = 0; ni < 4; ni++)
                wmma::load_matrix_sync(bf[ni], Bs + k8 * LDB + wn * 64 + ni * 16, LDB);
#pragma unroll
            for (int mi = 0; mi < 2; mi++)
#pragma unroll
                for (int ni = 0; ni < 4; ni++)
                    wmma::mma_sync(acc[mi][ni], af[mi], bf[ni], acc[mi][ni]);
        }
        __syncthreads();
    }

    // ---- epilogue: spill into cs (aliases slab buffers; dead now)
    float* cs = smf;
#pragma unroll
    for (int mi = 0; mi < 2; mi++)
#pragma unroll
        for (int ni = 0; ni < 4; ni++)
            wmma::store_matrix_sync(cs + (wm * 32 + mi * 16) * LDC + wn * 64 + ni * 16,
                                    acc[mi][ni], LDC, wmma::mem_row_major);
    __syncthreads();

    // LayerNorm stats: 4 threads per row
    const int r = tid >> 2, sub = tid & 3;
    float s = 0.f, s2 = 0.f;
#pragma unroll 8
    for (int j = 0; j < 64; j++) {
        int f = sub * 64 + j;
        float v = cs[r * LDC + f] + p_cb[f];
        s += v; s2 += v * v;
    }
    s  += __shfl_xor_sync(0xffffffffu, s, 1);
    s  += __shfl_xor_sync(0xffffffffu, s, 2);
    s2 += __shfl_xor_sync(0xffffffffu, s2, 1);
    s2 += __shfl_xor_sync(0xffffffffu, s2, 2);
    float mu  = s * (1.0f / Fc);
    float var = s2 * (1.0f / Fc) - mu * mu;
    float rs  = rsqrtf(var + 1e-5f);

    if (PASS == 1) {
        if (sub == 0) { p_mu[r] = mu; p_rs[r] = rs; }
        __syncthreads();
        // normalized + ReLU, tf32-rounded (it is conv2's A operand)
        for (int i = tid; i < MT * (Fc / 4); i += 256) {
            int r2 = i >> 6, c = (i & 63) << 2;
            float m = p_mu[r2], q = p_rs[r2];
            const float* cp = cs + r2 * LDC + c;
            float4 o;
            o.x = to_tf32(fmaxf((cp[0] + p_cb[c + 0] - m) * q * p_g[c + 0] + p_b[c + 0], 0.f));
            o.y = to_tf32(fmaxf((cp[1] + p_cb[c + 1] - m) * q * p_g[c + 1] + p_b[c + 1], 0.f));
            o.z = to_tf32(fmaxf((cp[2] + p_cb[c + 2] - m) * q * p_g[c + 2] + p_b[c + 2], 0.f));
            o.w = to_tf32(fmaxf((cp[3] + p_cb[c + 3] - m) * q * p_g[c + 3] + p_b[c + 3], 0.f));
            *(float4*)(g_h1 + ((size_t)b * Lc + l0 + r2) * Fc + c) = o;
        }
    } else {
        // fuse LN + ReLU + 256->1 linear + ReLU
        float dpv = 0.f;
#pragma unroll 8
        for (int j = 0; j < 64; j++) {
            int f = sub * 64 + j;
            float v = cs[r * LDC + f] + p_cb[f];
            float y = fmaxf((v - mu) * rs * p_g[f] + p_b[f], 0.f);
            dpv += y * p_lw[f];
        }
        dpv += __shfl_xor_sync(0xffffffffu, dpv, 1);
        dpv += __shfl_xor_sync(0xffffffffu, dpv, 2);
        if (sub == 0)
            dp[(size_t)b * Lc + l0 + r] = fmaxf(dpv + linb[0], 0.f);
    }
}

// ---------------------------------------------------------------------------
// Per-batch inclusive scan of durations (512 elems)
// ---------------------------------------------------------------------------
__global__ __launch_bounds__(512) void scan_kernel(const int* __restrict__ tgt)
{
    __shared__ int s[Lc];
    int b = blockIdx.x, tid = threadIdx.x;
    s[tid] = tgt[b * Lc + tid];
    __syncthreads();
    for (int off = 1; off < Lc; off <<= 1) {
        int v = (tid >= off) ? s[tid - off] : 0;
        __syncthreads();
        s[tid] += v;
        __syncthreads();
    }
    g_ends[b * Lc + tid] = s[tid];
}

// ---------------------------------------------------------------------------
// Length regulate: binary-search gather, zero past total. Streaming stores.
// ---------------------------------------------------------------------------
__global__ __launch_bounds__(256) void gather_kernel(
    const float* __restrict__ x, float* __restrict__ out, int T)
{
    __shared__ int se[Lc];
    __shared__ int sidx[64];
    int b = blockIdx.y, t0 = blockIdx.x * 64, tid = threadIdx.x;

    for (int i = tid; i < Lc; i += 256) se[i] = g_ends[b * Lc + i];
    __syncthreads();
    int total = se[Lc - 1];
    if (tid < 64) {
        int t = t0 + tid;
        int lo = 0, hi = Lc;
        while (lo < hi) {
            int mid = (lo + hi) >> 1;
            if (se[mid] <= t) lo = mid + 1; else hi = mid;
        }
        sidx[tid] = (t < total) ? min(lo, Lc - 1) : -1;
    }
    __syncthreads();

    int tx = tid & 63, ty = tid >> 6;
    const float4* x4 = reinterpret_cast<const float4*>(x + (size_t)b * Lc * Dc);
    float4* o4 = reinterpret_cast<float4*>(out + ((size_t)b * T + t0) * Dc);
#pragma unroll
    for (int tt = ty; tt < 64; tt += 4) {
        int j = sidx[tt];
        float4 v = make_float4(0.f, 0.f, 0.f, 0.f);
        if (j >= 0) v = x4[j * (Dc / 4) + tx];
        __stcs(&o4[tt * (Dc / 4) + tx], v);
    }
}

// ---------------------------------------------------------------------------
extern "C" void kernel_launch(void* const* d_in, const int* in_sizes, int n_in,
                              void* d_out, int out_size)
{
    int off = (n_in >= 13 && in_sizes[2] == 1) ? 1 : 0;
    const float* x   = (const float*)d_in[0];
    const int*   tgt = (const int*)d_in[1];
    const float* c1w = (const float*)d_in[2 + off];
    const float* c1b = (const float*)d_in[3 + off];
    const float* g1  = (const float*)d_in[4 + off];
    const float* b1  = (const float*)d_in[5 + off];
    const float* c2w = (const float*)d_in[6 + off];
    const float* c2b = (const float*)d_in[7 + off];
    const float* g2  = (const float*)d_in[8 + off];
    const float* b2  = (const float*)d_in[9 + off];
    const float* lw  = (const float*)d_in[10 + off];
    const float* lb  = (const float*)d_in[11 + off];

    float* out = (float*)d_out;
    int T = (out_size - Bc * Lc) / (Bc * Dc);   // 4096
    float* dp = out + (size_t)Bc * T * Dc;

    float *h1 = nullptr, *xr = nullptr, *wv = nullptr;
    cudaGetSymbolAddress((void**)&h1, g_h1);
    cudaGetSymbolAddress((void**)&xr, g_xr);
    cudaGetSymbolAddress((void**)&wv, g_w);

    size_t smem = (size_t)SMEMF * sizeof(float);   // 92672 B -> 2 CTAs/SM
    cudaFuncSetAttribute(conv_wmma<1>, cudaFuncAttributeMaxDynamicSharedMemorySize, (int)smem);
    cudaFuncSetAttribute(conv_wmma<2>, cudaFuncAttributeMaxDynamicSharedMemorySize, (int)smem);

    scan_kernel<<<Bc, Lc>>>(tgt);
    cvt_w<<<dim3(192, 2), 256>>>(c1w, c2w);
    cvt_x<<<8192, 256>>>(x);
    conv_wmma<1><<<dim3(Lc / MT, Bc), 256, smem>>>(
        xr, wv, c1b, g1, b1, nullptr, nullptr, nullptr);
    conv_wmma<2><<<dim3(Lc / MT, Bc), 256, smem>>>(
        h1, wv + 768 * Fc, c2b, g2, b2, lw, lb, dp);
    gather_kernel<<<dim3(T / 64, Bc), 256>>>(x, out, T);
}

// round 16
// speedup vs baseline: 2.4935x; 2.4935x over previous
#include <cuda_runtime.h>
#include <cuda_fp16.h>
#include <mma.h>
#include <cstdint>

using namespace nvcuda;

// Problem shape (fixed)
constexpr int Bc = 64, Lc = 512, Dc = 256, Fc = 256;
constexpr int MT = 64;            // output rows per CTA
constexpr int KS = 64;            // K slab (fp16)
constexpr int NSLAB = 768 / KS;   // 12
constexpr int LDA = 72;           // A slab stride (halfs): 144B, conflict-free ldmatrix
constexpr int LDB = 264;          // B slab stride (halfs): 528B
constexpr int LDC = 264;          // epilogue bounce stride (floats)

// SMEM byte layout (dynamic)
constexpr int ABUFB = MT * LDA * 2;         // 9216 B per A buffer
constexpr int OFFB  = 2 * ABUFB;            // 18432
constexpr int BBUFB = KS * LDB * 2;         // 33792 B per B buffer
constexpr int OFFP  = OFFB + 2 * BBUFB;     // 86016 (also >= 64*LDC*4 = 67584 for cs)
constexpr int SMEMB = OFFP + 1152 * 4;      // 90624 B -> 2 CTAs/SM

// Device scratch (no allocations allowed)
__device__ __half g_h1h[(size_t)Bc * Lc * Fc];  // conv1 out, fp16
__device__ __half g_xh[(size_t)Bc * Lc * Dc];   // x pre-converted to fp16
__device__ __half g_wh[2][768 * Fc];            // weights pre-converted to fp16
__device__ int    g_ends[Bc * Lc];
__device__ __align__(16) float g_zero[8];       // zero-initialized

// ---------------------------------------------------------------- helpers
__device__ __forceinline__ uint32_t smem_u32(const void* p) {
    uint32_t a;
    asm("{ .reg .u64 t; cvta.to.shared.u64 t, %1; cvt.u32.u64 %0, t; }" : "=r"(a) : "l"(p));
    return a;
}
__device__ __forceinline__ void cpa16(uint32_t dst, const void* src) {
    asm volatile("cp.async.ca.shared.global [%0], [%1], 16;" :: "r"(dst), "l"(src));
}
#define CPA_COMMIT() asm volatile("cp.async.commit_group;" ::: "memory")
#define CPA_WAIT(n)  asm volatile("cp.async.wait_group %0;" :: "n"(n) : "memory")

// ---------------------------------------------------------------------------
// Prep: convert weights / x to fp16 once
// ---------------------------------------------------------------------------
__global__ void cvt_w(const float* __restrict__ w1, const float* __restrict__ w2)
{
    int i = blockIdx.x * 256 + threadIdx.x;            // float4 idx, 49152 per w
    const float4* s = (const float4*)(blockIdx.y ? w2 : w1);
    float4 v = s[i];
    __half2* d = (__half2*)g_wh[blockIdx.y];
    d[i * 2 + 0] = __floats2half2_rn(v.x, v.y);
    d[i * 2 + 1] = __floats2half2_rn(v.z, v.w);
}
__global__ void cvt_x(const float* __restrict__ x)
{
    size_t i = (size_t)blockIdx.x * 256 + threadIdx.x; // float4 idx, 2097152
    float4 v = ((const float4*)x)[i];
    __half2* d = (__half2*)g_xh;
    d[i * 2 + 0] = __floats2half2_rn(v.x, v.y);
    d[i * 2 + 1] = __floats2half2_rn(v.z, v.w);
}

// ---------------------------------------------------------------------------
// Fused conv1d(k=3,same) -> bias -> LN -> ReLU (PASS1 -> g_h1h, fp16)
// PASS2 fuses the 256->1 linear + ReLU into dp.
// fp16 wmma m16n16k16, fp32 accum, cp.async double-buffered K=64 slabs,
// 2 CTAs/SM.
// ---------------------------------------------------------------------------
template <int PASS>
__global__ __launch_bounds__(256, 2) void conv_wmma(
    const __half* __restrict__ in,  // (B,L,256) fp16
    const __half* __restrict__ w,   // (768,256) fp16
    const float* __restrict__ cb,
    const float* __restrict__ gam,
    const float* __restrict__ bet,
    const float* __restrict__ linw,
    const float* __restrict__ linb,
    float* __restrict__ dp)
{
    extern __shared__ __align__(16) char smb[];
    __half* As0 = (__half*)smb;
    __half* Bs0 = (__half*)(smb + OFFB);
    float*  prm = (float*)(smb + OFFP);
    float* p_cb = prm;          float* p_g  = prm + 256;
    float* p_b  = prm + 512;    float* p_lw = prm + 768;
    float* p_mu = prm + 1024;   float* p_rs = prm + 1088;

    const uint32_t smA = smem_u32(smb);
    const uint32_t smB = smA + OFFB;

    const int tid = threadIdx.x;
    const int b   = blockIdx.y;
    const int l0  = blockIdx.x * MT;
    const __half* inb = in + (size_t)b * Lc * Dc;

    // ---- slab staging via cp.async (A: 64x64 with tap baked in; B: 64x256)
    auto stage = [&](int slab, int bufi) {
        const int tap = slab >> 2;            // 4 slabs per tap (256/64)
        const int kc0 = (slab & 3) * KS;
        const uint32_t ab = smA + (uint32_t)bufi * ABUFB;
#pragma unroll
        for (int t = 0; t < 2; t++) {         // A: 512 chunks of 16B (8 halfs)
            int i = tid + t * 256;
            int r = i >> 3, c = i & 7;
            int l = l0 + r - 1 + tap;
            const void* src = (l >= 0 && l < Lc)
                ? (const void*)(inb + (size_t)l * Dc + kc0 + c * 8)
                : (const void*)g_zero;
            cpa16(ab + (uint32_t)(r * LDA + c * 8) * 2, src);
        }
        const uint32_t bb = smB + (uint32_t)bufi * BBUFB;
        const __half* wsrc = w + (size_t)slab * KS * Fc;
#pragma unroll
        for (int t = 0; t < 8; t++) {         // B: 2048 chunks of 16B
            int i = tid + t * 256;
            int r = i >> 5, c = i & 31;
            cpa16(bb + (uint32_t)(r * LDB + c * 8) * 2, wsrc + (size_t)r * Fc + c * 8);
        }
    };

    // params (plain loads)
    for (int i = tid; i < Fc; i += 256) {
        p_cb[i] = cb[i]; p_g[i] = gam[i]; p_b[i] = bet[i];
        if (PASS == 2) p_lw[i] = linw[i];
    }

    const int wid = tid >> 5;
    const int wm = wid >> 2;          // 0..1 : 32 rows
    const int wn = wid & 3;           // 0..3 : 64 cols

    wmma::fragment<wmma::accumulator, 16, 16, 16, float> acc[2][4];
#pragma unroll
    for (int mi = 0; mi < 2; mi++)
#pragma unroll
        for (int ni = 0; ni < 4; ni++)
            wmma::fill_fragment(acc[mi][ni], 0.0f);

    stage(0, 0);
    CPA_COMMIT();

    for (int it = 0; it < NSLAB; ++it) {
        if (it + 1 < NSLAB) {
            stage(it + 1, (it + 1) & 1);
            CPA_COMMIT();
            CPA_WAIT(1);               // slab `it` landed; `it+1` in flight
        } else {
            CPA_WAIT(0);
        }
        __syncthreads();

        const __half* As = As0 + (it & 1) * (ABUFB / 2);
        const __half* Bs = Bs0 + (it & 1) * (BBUFB / 2);
#pragma unroll
        for (int k16 = 0; k16 < KS; k16 += 16) {
            wmma::fragment<wmma::matrix_a, 16, 16, 16, __half, wmma::row_major> af[2];
            wmma::fragment<wmma::matrix_b, 16, 16, 16, __half, wmma::row_major> bf[4];
#pragma unroll
            for (int mi = 0; mi < 2; mi++)
                wmma::load_matrix_sync(af[mi], As + (wm * 32 + mi * 16) * LDA + k16, LDA);
#pragma unroll
            for (int ni = 0; ni < 4; ni++)
                wmma::load_matrix_sync(bf[ni], Bs + k16 * LDB + wn * 64 + ni * 16, LDB);
#pragma unroll
            for (int mi = 0; mi < 2; mi++)
#pragma unroll
                for (int ni = 0; ni < 4; ni++)
                    wmma::mma_sync(acc[mi][ni], af[mi], bf[ni], acc[mi][ni]);
        }
        __syncthreads();
    }

    // ---- epilogue: spill into cs (aliases slab buffers; dead now)
    float* cs = (float*)smb;
#pragma unroll
    for (int mi = 0; mi < 2; mi++)
#pragma unroll
        for (int ni = 0; ni < 4; ni++)
            wmma::store_matrix_sync(cs + (wm * 32 + mi * 16) * LDC + wn * 64 + ni * 16,
                                    acc[mi][ni], LDC, wmma::mem_row_major);
    __syncthreads();

    // LayerNorm stats: 4 threads per row
    const int r = tid >> 2, sub = tid & 3;
    float s = 0.f, s2 = 0.f;
#pragma unroll 8
    for (int j = 0; j < 64; j++) {
        int f = sub * 64 + j;
        float v = cs[r * LDC + f] + p_cb[f];
        s += v; s2 += v * v;
    }
    s  += __shfl_xor_sync(0xffffffffu, s, 1);
    s  += __shfl_xor_sync(0xffffffffu, s, 2);
    s2 += __shfl_xor_sync(0xffffffffu, s2, 1);
    s2 += __shfl_xor_sync(0xffffffffu, s2, 2);
    float mu  = s * (1.0f / Fc);
    float var = s2 * (1.0f / Fc) - mu * mu;
    float rs  = rsqrtf(var + 1e-5f);

    if (PASS == 1) {
        if (sub == 0) { p_mu[r] = mu; p_rs[r] = rs; }
        __syncthreads();
        // normalized + ReLU -> fp16 (it is conv2's A operand)
        for (int i = tid; i < MT * (Fc / 4); i += 256) {
            int r2 = i >> 6, c = (i & 63) << 2;
            float m = p_mu[r2], q = p_rs[r2];
            const float* cp = cs + r2 * LDC + c;
            float ox = fmaxf((cp[0] + p_cb[c + 0] - m) * q * p_g[c + 0] + p_b[c + 0], 0.f);
            float oy = fmaxf((cp[1] + p_cb[c + 1] - m) * q * p_g[c + 1] + p_b[c + 1], 0.f);
            float oz = fmaxf((cp[2] + p_cb[c + 2] - m) * q * p_g[c + 2] + p_b[c + 2], 0.f);
            float ow = fmaxf((cp[3] + p_cb[c + 3] - m) * q * p_g[c + 3] + p_b[c + 3], 0.f);
            __half2* d = (__half2*)(g_h1h + ((size_t)b * Lc + l0 + r2) * Fc + c);
            d[0] = __floats2half2_rn(ox, oy);
            d[1] = __floats2half2_rn(oz, ow);
        }
    } else {
        // fuse LN + ReLU + 256->1 linear + ReLU
        float dpv = 0.f;
#pragma unroll 8
        for (int j = 0; j < 64; j++) {
            int f = sub * 64 + j;
            float v = cs[r * LDC + f] + p_cb[f];
            float y = fmaxf((v - mu) * rs * p_g[f] + p_b[f], 0.f);
            dpv += y * p_lw[f];
        }
        dpv += __shfl_xor_sync(0xffffffffu, dpv, 1);
        dpv += __shfl_xor_sync(0xffffffffu, dpv, 2);
        if (sub == 0)
            dp[(size_t)b * Lc + l0 + r] = fmaxf(dpv + linb[0], 0.f);
    }
}

// ---------------------------------------------------------------------------
// Per-batch inclusive scan of durations (512 elems)
// ---------------------------------------------------------------------------
__global__ __launch_bounds__(512) void scan_kernel(const int* __restrict__ tgt)
{
    __shared__ int s[Lc];
    int b = blockIdx.x, tid = threadIdx.x;
    s[tid] = tgt[b * Lc + tid];
    __syncthreads();
    for (int off = 1; off < Lc; off <<= 1) {
        int v = (tid >= off) ? s[tid - off] : 0;
        __syncthreads();
        s[tid] += v;
        __syncthreads();
    }
    g_ends[b * Lc + tid] = s[tid];
}

// ---------------------------------------------------------------------------
// Length regulate: binary-search gather, zero past total. Streaming stores.
// ---------------------------------------------------------------------------
__global__ __launch_bounds__(256) void gather_kernel(
    const float* __restrict__ x, float* __restrict__ out, int T)
{
    __shared__ int se[Lc];
    __shared__ int sidx[64];
    int b = blockIdx.y, t0 = blockIdx.x * 64, tid = threadIdx.x;

    for (int i = tid; i < Lc; i += 256) se[i] = g_ends[b * Lc + i];
    __syncthreads();
    int total = se[Lc - 1];
    if (tid < 64) {
        int t = t0 + tid;
        int lo = 0, hi = Lc;
        while (lo < hi) {
            int mid = (lo + hi) >> 1;
            if (se[mid] <= t) lo = mid + 1; else hi = mid;
        }
        sidx[tid] = (t < total) ? min(lo, Lc - 1) : -1;
    }
    __syncthreads();

    int tx = tid & 63, ty = tid >> 6;
    const float4* x4 = reinterpret_cast<const float4*>(x + (size_t)b * Lc * Dc);
    float4* o4 = reinterpret_cast<float4*>(out + ((size_t)b * T + t0) * Dc);
#pragma unroll
    for (int tt = ty; tt < 64; tt += 4) {
        int j = sidx[tt];
        float4 v = make_float4(0.f, 0.f, 0.f, 0.f);
        if (j >= 0) v = x4[j * (Dc / 4) + tx];
        __stcs(&o4[tt * (Dc / 4) + tx], v);
    }
}

// ---------------------------------------------------------------------------
extern "C" void kernel_launch(void* const* d_in, const int* in_sizes, int n_in,
                              void* d_out, int out_size)
{
    int off = (n_in >= 13 && in_sizes[2] == 1) ? 1 : 0;
    const float* x   = (const float*)d_in[0];
    const int*   tgt = (const int*)d_in[1];
    const float* c1w = (const float*)d_in[2 + off];
    const float* c1b = (const float*)d_in[3 + off];
    const float* g1  = (const float*)d_in[4 + off];
    const float* b1  = (const float*)d_in[5 + off];
    const float* c2w = (const float*)d_in[6 + off];
    const float* c2b = (const float*)d_in[7 + off];
    const float* g2  = (const float*)d_in[8 + off];
    const float* b2  = (const float*)d_in[9 + off];
    const float* lw  = (const float*)d_in[10 + off];
    const float* lb  = (const float*)d_in[11 + off];

    float* out = (float*)d_out;
    int T = (out_size - Bc * Lc) / (Bc * Dc);   // 4096
    float* dp = out + (size_t)Bc * T * Dc;

    __half *h1 = nullptr, *xh = nullptr, *wh = nullptr;
    cudaGetSymbolAddress((void**)&h1, g_h1h);
    cudaGetSymbolAddress((void**)&xh, g_xh);
    cudaGetSymbolAddress((void**)&wh, g_wh);

    size_t smem = SMEMB;   // 90624 B -> 2 CTAs/SM
    cudaFuncSetAttribute(conv_wmma<1>, cudaFuncAttributeMaxDynamicSharedMemorySize, (int)smem);
    cudaFuncSetAttribute(conv_wmma<2>, cudaFuncAttributeMaxDynamicSharedMemorySize, (int)smem);

    scan_kernel<<<Bc, Lc>>>(tgt);
    cvt_w<<<dim3(192, 2), 256>>>(c1w, c2w);
    cvt_x<<<8192, 256>>>(x);
    conv_wmma<1><<<dim3(Lc / MT, Bc), 256, smem>>>(
        xh, wh, c1b, g1, b1, nullptr, nullptr, nullptr);
    conv_wmma<2><<<dim3(Lc / MT, Bc), 256, smem>>>(
        h1, wh + 768 * Fc, c2b, g2, b2, lw, lb, dp);
    gather_kernel<<<dim3(T / 64, Bc), 256>>>(x, out, T);
}

// round 17
// speedup vs baseline: 2.5200x; 1.0106x over previous
#include <cuda_runtime.h>
#include <cuda_fp16.h>
#include <mma.h>
#include <cstdint>

using namespace nvcuda;

// Problem shape (fixed)
constexpr int Bc = 64, Lc = 512, Dc = 256, Fc = 256;
constexpr int MT = 64;            // output rows per CTA
constexpr int KS = 64;            // K slab (fp16)
constexpr int NSLAB = 768 / KS;   // 12
constexpr int LDA = 72;           // A slab stride (halfs): 144B, conflict-free ldmatrix
constexpr int LDB = 264;          // B slab stride (halfs): 528B
constexpr int LDC = 264;          // epilogue bounce stride (floats)

// SMEM byte layout (dynamic)
constexpr int ABUFB = MT * LDA * 2;         // 9216 B per A buffer
constexpr int OFFB  = 2 * ABUFB;            // 18432
constexpr int BBUFB = KS * LDB * 2;         // 33792 B per B buffer
constexpr int OFFP  = OFFB + 2 * BBUFB;     // 86016 (also >= 64*LDC*4 = 67584 for cs)
constexpr int SMEMB = OFFP + 1152 * 4;      // 90624 B -> 2 CTAs/SM

// Device scratch (no allocations allowed)
__device__ __half g_h1h[(size_t)Bc * Lc * Fc];  // conv1 out, fp16
__device__ __half g_xh[(size_t)Bc * Lc * Dc];   // x pre-converted to fp16
__device__ __half g_wh[2][768 * Fc];            // weights pre-converted to fp16
__device__ int    g_ends[Bc * Lc];
__device__ __align__(16) float g_zero[8];       // zero-initialized

// ---------------------------------------------------------------- helpers
__device__ __forceinline__ uint32_t smem_u32(const void* p) {
    uint32_t a;
    asm("{ .reg .u64 t; cvta.to.shared.u64 t, %1; cvt.u32.u64 %0, t; }" : "=r"(a) : "l"(p));
    return a;
}
__device__ __forceinline__ void cpa16(uint32_t dst, const void* src) {
    asm volatile("cp.async.ca.shared.global [%0], [%1], 16;" :: "r"(dst), "l"(src));
}
#define CPA_COMMIT() asm volatile("cp.async.commit_group;" ::: "memory")
#define CPA_WAIT(n)  asm volatile("cp.async.wait_group %0;" :: "n"(n) : "memory")

// ---------------------------------------------------------------------------
// Prep: convert weights / x to fp16 once
// ---------------------------------------------------------------------------
__global__ void cvt_w(const float* __restrict__ w1, const float* __restrict__ w2)
{
    int i = blockIdx.x * 256 + threadIdx.x;            // float4 idx, 49152 per w
    const float4* s = (const float4*)(blockIdx.y ? w2 : w1);
    float4 v = s[i];
    __half2* d = (__half2*)g_wh[blockIdx.y];
    d[i * 2 + 0] = __floats2half2_rn(v.x, v.y);
    d[i * 2 + 1] = __floats2half2_rn(v.z, v.w);
}
__global__ void cvt_x(const float* __restrict__ x)
{
    size_t i = (size_t)blockIdx.x * 256 + threadIdx.x; // float4 idx, 2097152
    float4 v = ((const float4*)x)[i];
    __half2* d = (__half2*)g_xh;
    d[i * 2 + 0] = __floats2half2_rn(v.x, v.y);
    d[i * 2 + 1] = __floats2half2_rn(v.z, v.w);
}

// ---------------------------------------------------------------------------
// Fused conv1d(k=3,same) -> bias -> LN -> ReLU (PASS1 -> g_h1h, fp16)
// PASS2 fuses the 256->1 linear + ReLU into dp.
// fp16 wmma m16n16k16, fp32 accum, cp.async double-buffered K=64 slabs,
// 2 CTAs/SM. Mainloop restructured for minimal live registers.
// ---------------------------------------------------------------------------
template <int PASS>
__global__ __launch_bounds__(256, 2) void conv_wmma(
    const __half* __restrict__ in,  // (B,L,256) fp16
    const __half* __restrict__ w,   // (768,256) fp16
    const float* __restrict__ cb,
    const float* __restrict__ gam,
    const float* __restrict__ bet,
    const float* __restrict__ linw,
    const float* __restrict__ linb,
    float* __restrict__ dp)
{
    extern __shared__ __align__(16) char smb[];
    __half* As0 = (__half*)smb;
    __half* Bs0 = (__half*)(smb + OFFB);
    float*  prm = (float*)(smb + OFFP);
    float* p_cb = prm;          float* p_g  = prm + 256;
    float* p_b  = prm + 512;    float* p_lw = prm + 768;
    float* p_mu = prm + 1024;   float* p_rs = prm + 1088;

    const uint32_t smA = smem_u32(smb);
    const uint32_t smB = smA + OFFB;

    const int tid = threadIdx.x;
    const int b   = blockIdx.y;
    const int l0  = blockIdx.x * MT;
    const __half* inb = in + (size_t)b * Lc * Dc;

    // ---- precomputed per-thread staging addresses (loop-invariant)
    // A: thread covers rows rA0 (+64-row strided second chunk is r+32? no: 2
    //    chunks of 256 threads cover 512 16B-chunks = 64 rows x 8 chunks)
    const int arow = tid >> 3, acol = (tid & 7) * 8;          // chunk 0
    const int lA0  = l0 + arow - 1;                            // + tap
    const uint32_t aDst0 = smA + (uint32_t)(arow * LDA + acol) * 2;
    const int arow1 = arow + 32;
    const int lA1  = l0 + arow1 - 1;
    const uint32_t aDst1 = smA + (uint32_t)(arow1 * LDA + acol) * 2;
    // B: 8 chunks per thread
    const int brow = tid >> 5, bcol = (tid & 31) * 8;
    const uint32_t bDst0 = smB + (uint32_t)(brow * LDB + bcol) * 2;
    const __half* bSrc0 = w + (size_t)brow * Fc + bcol;

    auto stage = [&](int slab, int bufi) {
        const int tap = slab >> 2;            // 4 slabs per tap (256/64)
        const int kc0 = (slab & 3) * KS;
        const uint32_t ab = (uint32_t)bufi * ABUFB;
        {
            int l = lA0 + tap;
            const void* src = (l >= 0 && l < Lc)
                ? (const void*)(inb + (size_t)l * Dc + kc0 + acol) : (const void*)g_zero;
            cpa16(aDst0 + ab, src);
            l = lA1 + tap;
            src = (l >= 0 && l < Lc)
                ? (const void*)(inb + (size_t)l * Dc + kc0 + acol) : (const void*)g_zero;
            cpa16(aDst1 + ab, src);
        }
        const uint32_t bb = (uint32_t)bufi * BBUFB;
        const __half* ws = bSrc0 + (size_t)slab * KS * Fc;
#pragma unroll
        for (int t = 0; t < 8; t++)
            cpa16(bDst0 + bb + (uint32_t)(t * 8 * LDB) * 2, ws + (size_t)t * 8 * Fc);
    };

    // params (plain loads)
    for (int i = tid; i < Fc; i += 256) {
        p_cb[i] = cb[i]; p_g[i] = gam[i]; p_b[i] = bet[i];
        if (PASS == 2) p_lw[i] = linw[i];
    }

    const int wid = tid >> 5;
    const int wm = wid >> 2;          // 0..1 : 32 rows
    const int wn = wid & 3;           // 0..3 : 64 cols

    wmma::fragment<wmma::accumulator, 16, 16, 16, float> acc[2][4];
#pragma unroll
    for (int mi = 0; mi < 2; mi++)
#pragma unroll
        for (int ni = 0; ni < 4; ni++)
            wmma::fill_fragment(acc[mi][ni], 0.0f);

    stage(0, 0);
    CPA_COMMIT();

    for (int it = 0; it < NSLAB; ++it) {
        if (it + 1 < NSLAB) {
            stage(it + 1, (it + 1) & 1);
            CPA_COMMIT();
            CPA_WAIT(1);               // slab `it` landed; `it+1` in flight
        } else {
            CPA_WAIT(0);
        }
        __syncthreads();

        const __half* As = As0 + (it & 1) * (ABUFB / 2) + (wm * 32) * LDA;
        const __half* Bs = Bs0 + (it & 1) * (BBUFB / 2) + wn * 64;
#pragma unroll
        for (int k16 = 0; k16 < KS; k16 += 16) {
            wmma::fragment<wmma::matrix_a, 16, 16, 16, __half, wmma::row_major> af[2];
            wmma::load_matrix_sync(af[0], As + k16, LDA);
            wmma::load_matrix_sync(af[1], As + 16 * LDA + k16, LDA);
#pragma unroll
            for (int ni = 0; ni < 4; ni++) {
                wmma::fragment<wmma::matrix_b, 16, 16, 16, __half, wmma::row_major> bf;
                wmma::load_matrix_sync(bf, Bs + k16 * LDB + ni * 16, LDB);
                wmma::mma_sync(acc[0][ni], af[0], bf, acc[0][ni]);
                wmma::mma_sync(acc[1][ni], af[1], bf, acc[1][ni]);
            }
        }
        __syncthreads();
    }

    // ---- epilogue: spill into cs (aliases slab buffers; dead now)
    float* cs = (float*)smb;
#pragma unroll
    for (int mi = 0; mi < 2; mi++)
#pragma unroll
        for (int ni = 0; ni < 4; ni++)
            wmma::store_matrix_sync(cs + (wm * 32 + mi * 16) * LDC + wn * 64 + ni * 16,
                                    acc[mi][ni], LDC, wmma::mem_row_major);
    __syncthreads();

    // LayerNorm stats: 4 threads per row
    const int r = tid >> 2, sub = tid & 3;
    float s = 0.f, s2 = 0.f;
#pragma unroll 8
    for (int j = 0; j < 64; j++) {
        int f = sub * 64 + j;
        float v = cs[r * LDC + f] + p_cb[f];
        s += v; s2 += v * v;
    }
    s  += __shfl_xor_sync(0xffffffffu, s, 1);
    s  += __shfl_xor_sync(0xffffffffu, s, 2);
    s2 += __shfl_xor_sync(0xffffffffu, s2, 1);
    s2 += __shfl_xor_sync(0xffffffffu, s2, 2);
    float mu  = s * (1.0f / Fc);
    float var = s2 * (1.0f / Fc) - mu * mu;
    float rs  = rsqrtf(var + 1e-5f);

    if (PASS == 1) {
        if (sub == 0) { p_mu[r] = mu; p_rs[r] = rs; }
        __syncthreads();
        // normalized + ReLU -> fp16 (it is conv2's A operand)
        for (int i = tid; i < MT * (Fc / 4); i += 256) {
            int r2 = i >> 6, c = (i & 63) << 2;
            float m = p_mu[r2], q = p_rs[r2];
            const float* cp = cs + r2 * LDC + c;
            float ox = fmaxf((cp[0] + p_cb[c + 0] - m) * q * p_g[c + 0] + p_b[c + 0], 0.f);
            float oy = fmaxf((cp[1] + p_cb[c + 1] - m) * q * p_g[c + 1] + p_b[c + 1], 0.f);
            float oz = fmaxf((cp[2] + p_cb[c + 2] - m) * q * p_g[c + 2] + p_b[c + 2], 0.f);
            float ow = fmaxf((cp[3] + p_cb[c + 3] - m) * q * p_g[c + 3] + p_b[c + 3], 0.f);
            __half2* d = (__half2*)(g_h1h + ((size_t)b * Lc + l0 + r2) * Fc + c);
            d[0] = __floats2half2_rn(ox, oy);
            d[1] = __floats2half2_rn(oz, ow);
        }
    } else {
        // fuse LN + ReLU + 256->1 linear + ReLU
        float dpv = 0.f;
#pragma unroll 8
        for (int j = 0; j < 64; j++) {
            int f = sub * 64 + j;
            float v = cs[r * LDC + f] + p_cb[f];
            float y = fmaxf((v - mu) * rs * p_g[f] + p_b[f], 0.f);
            dpv += y * p_lw[f];
        }
        dpv += __shfl_xor_sync(0xffffffffu, dpv, 1);
        dpv += __shfl_xor_sync(0xffffffffu, dpv, 2);
        if (sub == 0)
            dp[(size_t)b * Lc + l0 + r] = fmaxf(dpv + linb[0], 0.f);
    }
}

// ---------------------------------------------------------------------------
// Per-batch inclusive scan of durations (512 elems)
// ---------------------------------------------------------------------------
__global__ __launch_bounds__(512) void scan_kernel(const int* __restrict__ tgt)
{
    __shared__ int s[Lc];
    int b = blockIdx.x, tid = threadIdx.x;
    s[tid] = tgt[b * Lc + tid];
    __syncthreads();
    for (int off = 1; off < Lc; off <<= 1) {
        int v = (tid >= off) ? s[tid - off] : 0;
        __syncthreads();
        s[tid] += v;
        __syncthreads();
    }
    g_ends[b * Lc + tid] = s[tid];
}

// ---------------------------------------------------------------------------
// Length regulate: binary-search gather, zero past total. Streaming stores.
// ---------------------------------------------------------------------------
__global__ __launch_bounds__(256) void gather_kernel(
    const float* __restrict__ x, float* __restrict__ out, int T)
{
    __shared__ int se[Lc];
    __shared__ int sidx[64];
    int b = blockIdx.y, t0 = blockIdx.x * 64, tid = threadIdx.x;

    for (int i = tid; i < Lc; i += 256) se[i] = g_ends[b * Lc + i];
    __syncthreads();
    int total = se[Lc - 1];
    if (tid < 64) {
        int t = t0 + tid;
        int lo = 0, hi = Lc;
        while (lo < hi) {
            int mid = (lo + hi) >> 1;
            if (se[mid] <= t) lo = mid + 1; else hi = mid;
        }
        sidx[tid] = (t < total) ? min(lo, Lc - 1) : -1;
    }
    __syncthreads();

    int tx = tid & 63, ty = tid >> 6;
    const float4* x4 = reinterpret_cast<const float4*>(x + (size_t)b * Lc * Dc);
    float4* o4 = reinterpret_cast<float4*>(out + ((size_t)b * T + t0) * Dc);
#pragma unroll
    for (int tt = ty; tt < 64; tt += 4) {
        int j = sidx[tt];
        float4 v = make_float4(0.f, 0.f, 0.f, 0.f);
        if (j >= 0) v = x4[j * (Dc / 4) + tx];
        __stcs(&o4[tt * (Dc / 4) + tx], v);
    }
}

// ---------------------------------------------------------------------------
extern "C" void kernel_launch(void* const* d_in, const int* in_sizes, int n_in,
                              void* d_out, int out_size)
{
    int off = (n_in >= 13 && in_sizes[2] == 1) ? 1 : 0;
    const float* x   = (const float*)d_in[0];
    const int*   tgt = (const int*)d_in[1];
    const float* c1w = (const float*)d_in[2 + off];
    const float* c1b = (const float*)d_in[3 + off];
    const float* g1  = (const float*)d_in[4 + off];
    const float* b1  = (const float*)d_in[5 + off];
    const float* c2w = (const float*)d_in[6 + off];
    const float* c2b = (const float*)d_in[7 + off];
    const float* g2  = (const float*)d_in[8 + off];
    const float* b2  = (const float*)d_in[9 + off];
    const float* lw  = (const float*)d_in[10 + off];
    const float* lb  = (const float*)d_in[11 + off];

    float* out = (float*)d_out;
    int T = (out_size - Bc * Lc) / (Bc * Dc);   // 4096
    float* dp = out + (size_t)Bc * T * Dc;

    __half *h1 = nullptr, *xh = nullptr, *wh = nullptr;
    cudaGetSymbolAddress((void**)&h1, g_h1h);
    cudaGetSymbolAddress((void**)&xh, g_xh);
    cudaGetSymbolAddress((void**)&wh, g_wh);

    size_t smem = SMEMB;   // 90624 B -> 2 CTAs/SM
    cudaFuncSetAttribute(conv_wmma<1>, cudaFuncAttributeMaxDynamicSharedMemorySize, (int)smem);
    cudaFuncSetAttribute(conv_wmma<2>, cudaFuncAttributeMaxDynamicSharedMemorySize, (int)smem);

    scan_kernel<<<Bc, Lc>>>(tgt);
    cvt_w<<<dim3(192, 2), 256>>>(c1w, c2w);
    cvt_x<<<8192, 256>>>(x);
    conv_wmma<1><<<dim3(Lc / MT, Bc), 256, smem>>>(
        xh, wh, c1b, g1, b1, nullptr, nullptr, nullptr);
    conv_wmma<2><<<dim3(Lc / MT, Bc), 256, smem>>>(
        h1, wh + 768 * Fc, c2b, g2, b2, lw, lb, dp);
    gather_kernel<<<dim3(T / 64, Bc), 256>>>(x, out, T);
}